// round 8
// baseline (speedup 1.0000x reference)
#include <cuda_runtime.h>
#include <cuda_bf16.h>
#include <math.h>
#include <cstdint>

#define BN 8192
#define DD 128
#define NT 64                       // 64 h-blocks of 128 rows
#define NPAIRU 1056                 // paired-j triangular units
#define NUNITS (3 + NT + NPAIRU)    // 1123
#define GRID 304
#define FARV (-0.00995033085316808285f)

// smem layout (dynamic, 102400 B): header 4KB + three 32KB tiles
#define AO 4096
#define BO 36864
#define WO 69632
#define SMEM_ALL 102400
#define H_RED  0
#define H_SQI  64
#define H_SQJ0 576
#define H_SQJ1 1088
#define H_YI   1600
#define H_YJ0  2112
#define H_YJ1  2624
#define H_BIAS 3136

// Device state (zero-initialized at load; reset by last CTA each run)
__device__ __nv_bfloat16 g_h[BN*DD];       // swizzled-row layout
__device__ __nv_bfloat16 g_wt[3][DD*DD];   // W^T, swizzled-row layout
__device__ float  g_sq[BN];
__device__ double g_loss;
__device__ double g_hsum;
__device__ unsigned g_work;
__device__ unsigned g_exit;
__device__ unsigned g_done[NT];
__device__ unsigned g_wdone[3];

// ---------------- warp-MMA helpers (plain sm_80+ PTX) ----------------------
__device__ __forceinline__ void ldm_x4(uint32_t& r0, uint32_t& r1,
                                       uint32_t& r2, uint32_t& r3, uint32_t addr) {
    asm volatile("ldmatrix.sync.aligned.m8n8.x4.shared.b16 {%0,%1,%2,%3}, [%4];"
                 : "=r"(r0), "=r"(r1), "=r"(r2), "=r"(r3) : "r"(addr));
}
__device__ __forceinline__ void mma_bf16(float* d, const uint32_t* a, const uint32_t* b) {
    asm volatile("mma.sync.aligned.m16n8k16.row.col.f32.bf16.bf16.f32 "
                 "{%0,%1,%2,%3}, {%4,%5,%6,%7}, {%8,%9}, {%0,%1,%2,%3};"
                 : "+f"(d[0]), "+f"(d[1]), "+f"(d[2]), "+f"(d[3])
                 : "r"(a[0]), "r"(a[1]), "r"(a[2]), "r"(a[3]), "r"(b[0]), "r"(b[1]));
}
__device__ __forceinline__ uint32_t smem_to_u32(const void* p) {
    uint32_t a;
    asm("{ .reg .u64 t; cvta.to.shared.u64 t, %1; cvt.u32.u64 %0, t; }" : "=r"(a) : "l"(p));
    return a;
}

__device__ __forceinline__ void wait_flag(unsigned* f) {
    if (threadIdx.x == 0) {
        while (atomicAdd(f, 0u) == 0u) __nanosleep(100);
        __threadfence();
    }
    __syncthreads();
}

// 128x128x128 bf16 MMA tile: 8 warps (wr 0..3 x wc 0..1), acc[2][8][4].
__device__ __forceinline__ void tile_mma(const char* smc, int aOff, int bOff,
                                         float acc[2][8][4], int lane, int wr, int wc) {
    uint32_t aB = smem_to_u32(smc + aOff);
    uint32_t bB = smem_to_u32(smc + bOff);
    #pragma unroll
    for (int mt = 0; mt < 2; mt++)
        #pragma unroll
        for (int nt = 0; nt < 8; nt++)
            #pragma unroll
            for (int k = 0; k < 4; k++) acc[mt][nt][k] = 0.0f;

    int aRow0 = wr*32 + (lane & 15);
    int aSel  = lane >> 4;
    int bg    = lane >> 3;
    int bRow0 = wc*64 + ((bg >> 1) << 3) + (lane & 7);
    int bSel  = bg & 1;

    #pragma unroll 1
    for (int ks = 0; ks < 8; ks++) {
        uint32_t a[2][4];
        #pragma unroll
        for (int mt = 0; mt < 2; mt++) {
            int row = aRow0 + mt*16;
            uint32_t addr = aB + (uint32_t)row*256
                          + (uint32_t)((((ks << 1) | aSel) ^ (row & 7)) << 4);
            ldm_x4(a[mt][0], a[mt][1], a[mt][2], a[mt][3], addr);
        }
        uint32_t b[8][2];
        #pragma unroll
        for (int np = 0; np < 4; np++) {
            int row = bRow0 + np*16;
            uint32_t addr = bB + (uint32_t)row*256
                          + (uint32_t)((((ks << 1) | bSel) ^ (row & 7)) << 4);
            uint32_t r0, r1, r2, r3;
            ldm_x4(r0, r1, r2, r3, addr);
            b[2*np][0] = r0;   b[2*np][1] = r1;
            b[2*np+1][0] = r2; b[2*np+1][1] = r3;
        }
        #pragma unroll
        for (int mt = 0; mt < 2; mt++)
            #pragma unroll
            for (int nt = 0; nt < 8; nt++)
                mma_bf16(acc[mt][nt], a[mt], b[nt]);
    }
}

// Pair-tile loss epilogue: branchless + deferred rare fixup. Returns thread sum.
__device__ __forceinline__ float tile_loss(char* smc, float acc[2][8][4],
                                           int sqjOff, int yjOff,
                                           int lane, int wr, int wc) {
    float* sqi = (float*)(smc + H_SQI);
    int*   yi  = (int*)(smc + H_YI);
    float* sqj = (float*)(smc + sqjOff);
    int*   yj  = (int*)(smc + yjOff);

    int r8 = lane >> 2, c2 = (lane & 3) << 1;
    float si[2][2]; int li[2][2];
    #pragma unroll
    for (int mt = 0; mt < 2; mt++)
        #pragma unroll
        for (int h = 0; h < 2; h++) {
            int row = wr*32 + mt*16 + h*8 + r8;
            si[mt][h] = sqi[row];
            li[mt][h] = yi[row];
        }
    float sj[8][2]; int lj[8][2];
    #pragma unroll
    for (int nt = 0; nt < 8; nt++)
        #pragma unroll
        for (int q = 0; q < 2; q++) {
            int col = wc*64 + nt*8 + c2 + q;
            sj[nt][q] = sqj[col];
            lj[nt][q] = yj[col];
        }

    float lsum = 0.0f;
    int rare = 0;
    #pragma unroll
    for (int mt = 0; mt < 2; mt++)
        #pragma unroll
        for (int nt = 0; nt < 8; nt++)
            #pragma unroll
            for (int h = 0; h < 2; h++)
                #pragma unroll
                for (int q = 0; q < 2; q++) {
                    float d = acc[mt][nt][h*2 + q];
                    float dist = fmaxf(fmaf(-2.0f, d, si[mt][h] + sj[nt][q]), 0.0f);
                    bool  eq = (li[mt][h] == lj[nt][q]);
                    lsum += eq ? dist : FARV;
                    rare |= (!eq && dist < 18.0f);
                }
    if (__any_sync(0xffffffffu, rare)) {
        #pragma unroll
        for (int mt = 0; mt < 2; mt++)
            #pragma unroll
            for (int nt = 0; nt < 8; nt++)
                #pragma unroll
                for (int h = 0; h < 2; h++)
                    #pragma unroll
                    for (int q = 0; q < 2; q++) {
                        float d = acc[mt][nt][h*2 + q];
                        float dist = fmaxf(fmaf(-2.0f, d, si[mt][h] + sj[nt][q]), 0.0f);
                        bool  eq = (li[mt][h] == lj[nt][q]);
                        if (!eq && dist < 18.0f)
                            lsum += (-logf(1.01f - expf(-dist))) - FARV;
                    }
    }
    return lsum;
}

// MLP layer store: bias add (+relu), bf16 RN round, write swizzled to outOff.
// LAST also accumulates per-row |h~|^2 into sq_sm (header H_SQI).
template<bool RELU, bool LAST>
__device__ __forceinline__ void mlp_store(char* smc, int outOff, float acc[2][8][4],
                                          int lane, int wr, int wc) {
    const float* biasf = (const float*)(smc + H_BIAS);
    float* sq_sm = (float*)(smc + H_SQI);
    int r8 = lane >> 2, c2 = (lane & 3) << 1;
    #pragma unroll
    for (int mt = 0; mt < 2; mt++) {
        float srow[2] = {0.0f, 0.0f};
        #pragma unroll
        for (int nt = 0; nt < 8; nt++) {
            int col = wc*64 + nt*8 + c2;
            float b0 = biasf[col], b1 = biasf[col + 1];
            #pragma unroll
            for (int h8 = 0; h8 < 2; h8++) {
                float f0 = acc[mt][nt][h8*2]     + b0;
                float f1 = acc[mt][nt][h8*2 + 1] + b1;
                if (RELU) { f0 = fmaxf(f0, 0.0f); f1 = fmaxf(f1, 0.0f); }
                __nv_bfloat162 p = __float22bfloat162_rn(make_float2(f0, f1));
                uint32_t pk = *(const uint32_t*)&p;
                int r = wr*32 + mt*16 + h8*8 + r8;
                int chunk = wc*8 + nt;
                uint32_t off = (uint32_t)outOff + (uint32_t)r*256
                             + (uint32_t)((chunk ^ (r & 7)) << 4) + (uint32_t)c2*2;
                *(uint32_t*)(smc + off) = pk;
                if (LAST) {
                    float2 fb = __bfloat1622float2(p);
                    srow[h8] += fb.x*fb.x + fb.y*fb.y;
                }
            }
        }
        if (LAST) {
            #pragma unroll
            for (int h8 = 0; h8 < 2; h8++) {
                float s = srow[h8];
                s += __shfl_xor_sync(0xffffffffu, s, 1);
                s += __shfl_xor_sync(0xffffffffu, s, 2);
                if ((lane & 3) == 0)
                    atomicAdd(&sq_sm[wr*32 + mt*16 + h8*8 + r8], s);
            }
        }
    }
}

// ---------------------------------------------------------------------------

__global__ void __launch_bounds__(256, 2)
k_all(const float* __restrict__ X,
      const float* __restrict__ W1, const float* __restrict__ b1,
      const float* __restrict__ W2, const float* __restrict__ b2,
      const float* __restrict__ W3, const float* __restrict__ b3,
      const int* __restrict__ y, float* __restrict__ out) {
    extern __shared__ char smc[];
    __shared__ unsigned s_u;
    int tid = threadIdx.x, wid = tid >> 5, lane = tid & 31;
    int wr = wid & 3, wc = wid >> 2;

    while (true) {
        if (tid == 0) s_u = atomicAdd(&g_work, 1u);
        __syncthreads();
        unsigned u = s_u;
        if (u >= NUNITS) break;

        if (u < 3) {
            // ---- W-transpose unit: coalesced stage + transpose+round ----
            const float* W = (u == 0) ? W1 : (u == 1) ? W2 : W3;
            float* stage = (float*)(smc + AO);          // 64KB fp32 stage
            const float4* ws = (const float4*)W;
            float4* st4 = (float4*)stage;
            for (int e = tid; e < 4096; e += 256) st4[e] = ws[e];
            __syncthreads();
            uint4* dst = (uint4*)g_wt[u];
            for (int cid = tid; cid < 2048; cid += 256) {
                int c = cid >> 7, n = cid & 127;
                uint32_t pk[4];
                #pragma unroll
                for (int p = 0; p < 4; p++) {
                    float lo = stage[(c*8 + 2*p    ) * DD + n];
                    float hi = stage[(c*8 + 2*p + 1) * DD + n];
                    __nv_bfloat162 h2 = __float22bfloat162_rn(make_float2(lo, hi));
                    pk[p] = *(const uint32_t*)&h2;
                }
                dst[n*16 + (c ^ (n & 7))] = make_uint4(pk[0], pk[1], pk[2], pk[3]);
            }
            __threadfence();
            __syncthreads();
            if (tid == 0) atomicExch(&g_wdone[u], 1u);
        } else if (u < 3 + NT) {
            // ---- MLP unit: 128 rows, 3 layers of 128x128x128 HMMA ----
            int b = (int)u - 3;
            int r0 = b * 128;
            if (tid < 128) ((float*)(smc + H_SQI))[tid] = 0.0f;

            // load X rows fp32 coalesced, round bf16, store swizzled to A
            const float4* src = (const float4*)(X + r0*DD);
            uint4* Asm = (uint4*)(smc + AO);
            for (int e = tid; e < 2048; e += 256) {
                int row = e >> 4, c = e & 15;
                float4 v0 = src[row*32 + c*2];
                float4 v1 = src[row*32 + c*2 + 1];
                __nv_bfloat162 p0 = __float22bfloat162_rn(make_float2(v0.x, v0.y));
                __nv_bfloat162 p1 = __float22bfloat162_rn(make_float2(v0.z, v0.w));
                __nv_bfloat162 p2 = __float22bfloat162_rn(make_float2(v1.x, v1.y));
                __nv_bfloat162 p3 = __float22bfloat162_rn(make_float2(v1.z, v1.w));
                Asm[row*16 + (c ^ (row & 7))] =
                    make_uint4(*(const uint32_t*)&p0, *(const uint32_t*)&p1,
                               *(const uint32_t*)&p2, *(const uint32_t*)&p3);
            }

            uint4* Wsm = (uint4*)(smc + WO);
            float* biasf = (float*)(smc + H_BIAS);
            float acc[2][8][4];

            // layer 1: A -> B
            wait_flag(&g_wdone[0]);
            for (int e = tid; e < 2048; e += 256) Wsm[e] = ((const uint4*)g_wt[0])[e];
            if (tid < DD) biasf[tid] = b1[tid];
            __syncthreads();
            tile_mma(smc, AO, WO, acc, lane, wr, wc);
            mlp_store<true, false>(smc, BO, acc, lane, wr, wc);
            __syncthreads();

            // layer 2: B -> A
            wait_flag(&g_wdone[1]);
            for (int e = tid; e < 2048; e += 256) Wsm[e] = ((const uint4*)g_wt[1])[e];
            if (tid < DD) biasf[tid] = b2[tid];
            __syncthreads();
            tile_mma(smc, BO, WO, acc, lane, wr, wc);
            mlp_store<true, false>(smc, AO, acc, lane, wr, wc);
            __syncthreads();

            // layer 3: A -> B (no relu), sq from rounded values
            wait_flag(&g_wdone[2]);
            for (int e = tid; e < 2048; e += 256) Wsm[e] = ((const uint4*)g_wt[2])[e];
            if (tid < DD) biasf[tid] = b3[tid];
            __syncthreads();
            tile_mma(smc, AO, WO, acc, lane, wr, wc);
            mlp_store<false, true>(smc, BO, acc, lane, wr, wc);
            __syncthreads();

            // write h block (already swizzled) + sq + hsum
            for (int e = tid; e < 2048; e += 256)
                ((uint4*)g_h)[r0*16 + e] = ((uint4*)(smc + BO))[e];
            if (tid < 128) {
                float sv = ((float*)(smc + H_SQI))[tid];
                g_sq[r0 + tid] = sv;
                sv += __shfl_xor_sync(0xffffffffu, sv, 16);
                sv += __shfl_xor_sync(0xffffffffu, sv, 8);
                sv += __shfl_xor_sync(0xffffffffu, sv, 4);
                sv += __shfl_xor_sync(0xffffffffu, sv, 2);
                sv += __shfl_xor_sync(0xffffffffu, sv, 1);
                if (lane == 0) atomicAdd(&g_hsum, (double)sv);
            }
            __threadfence();
            __syncthreads();
            if (tid == 0) atomicExch(&g_done[b], 1u);
        } else {
            // ---- pair unit: tiles (bi,bj0) and (bi,bj0+1) sharing Hi ----
            int rem = (int)u - (3 + NT);
            int bi = 0;
            while (true) {
                int np = (65 - bi) >> 1;
                if (rem < np) break;
                rem -= np; bi++;
            }
            int bj0 = bi + 2*rem;
            bool has2 = (bj0 + 1 < NT);

            wait_flag(&g_done[bi]);
            wait_flag(&g_done[bj0]);
            if (has2) wait_flag(&g_done[bj0 + 1]);

            const uint4* gh = (const uint4*)g_h;
            uint4* Hi  = (uint4*)(smc + AO);
            uint4* Hj0 = (uint4*)(smc + BO);
            uint4* Hj1 = (uint4*)(smc + WO);
            for (int e = tid; e < 2048; e += 256) {
                Hi[e]  = gh[bi*2048 + e];
                Hj0[e] = gh[bj0*2048 + e];
                if (has2) Hj1[e] = gh[(bj0+1)*2048 + e];
            }
            if (tid < 128) {
                ((float*)(smc + H_SQI))[tid]  = g_sq[bi*128 + tid];
                ((int*)(smc + H_YI))[tid]     = y[bi*128 + tid];
                ((float*)(smc + H_SQJ0))[tid] = g_sq[bj0*128 + tid];
                ((int*)(smc + H_YJ0))[tid]    = y[bj0*128 + tid];
                if (has2) {
                    ((float*)(smc + H_SQJ1))[tid] = g_sq[(bj0+1)*128 + tid];
                    ((int*)(smc + H_YJ1))[tid]    = y[(bj0+1)*128 + tid];
                }
            }
            __syncthreads();

            float lsum = 0.0f;
            {
                float acc[2][8][4];
                tile_mma(smc, AO, BO, acc, lane, wr, wc);
                float ls = tile_loss(smc, acc, H_SQJ0, H_YJ0, lane, wr, wc);
                lsum += (bj0 == bi) ? ls : 2.0f*ls;
            }
            if (has2) {
                float acc[2][8][4];
                tile_mma(smc, AO, WO, acc, lane, wr, wc);
                float ls = tile_loss(smc, acc, H_SQJ1, H_YJ1, lane, wr, wc);
                lsum += 2.0f*ls;   // bj0+1 > bi always
            }

            lsum += __shfl_xor_sync(0xffffffffu, lsum, 1);
            lsum += __shfl_xor_sync(0xffffffffu, lsum, 2);
            lsum += __shfl_xor_sync(0xffffffffu, lsum, 4);
            lsum += __shfl_xor_sync(0xffffffffu, lsum, 8);
            lsum += __shfl_xor_sync(0xffffffffu, lsum, 16);
            if (lane == 0) ((float*)(smc + H_RED))[wid] = lsum;
            __syncthreads();
            if (tid == 0) {
                float* redf = (float*)(smc + H_RED);
                double tot = 0.0;
                for (int w = 0; w < 8; w++) tot += (double)redf[w];
                atomicAdd(&g_loss, tot);
            }
        }
        __syncthreads();
    }

    // exit: last CTA finalizes and resets state for the next replay
    if (tid == 0) {
        __threadfence();
        unsigned e = atomicAdd(&g_exit, 1u);
        if (e == GRID - 1) {
            __threadfence();
            double lt = atomicAdd(&g_loss, 0.0);
            double hs = atomicAdd(&g_hsum, 0.0);
            double loss = lt / ((double)BN * (double)BN);
            loss += 0.01 * (hs / ((double)BN * (double)DD));
            out[0] = (float)loss;
            g_loss = 0.0; g_hsum = 0.0; g_work = 0u;
            for (int i = 0; i < NT; i++) g_done[i] = 0u;
            g_wdone[0] = 0u; g_wdone[1] = 0u; g_wdone[2] = 0u;
            __threadfence();
            atomicExch(&g_exit, 0u);
        }
    }
}

// ---------------------------------------------------------------------------

extern "C" void kernel_launch(void* const* d_in, const int* in_sizes, int n_in,
                              void* d_out, int out_size) {
    (void)in_sizes; (void)n_in; (void)out_size;
    const float* X  = (const float*)d_in[0];
    const float* W1 = (const float*)d_in[1];
    const float* b1 = (const float*)d_in[2];
    const float* W2 = (const float*)d_in[3];
    const float* b2 = (const float*)d_in[4];
    const float* W3 = (const float*)d_in[5];
    const float* b3 = (const float*)d_in[6];
    const int*   y  = (const int*)d_in[7];

    cudaFuncSetAttribute(k_all, cudaFuncAttributeMaxDynamicSharedMemorySize, SMEM_ALL);
    k_all<<<GRID, 256, SMEM_ALL>>>(X, W1, b1, W2, b2, W3, b3, y, (float*)d_out);
}

// round 12
// speedup vs baseline: 1.4061x; 1.4061x over previous
#include <cuda_runtime.h>
#include <cuda_bf16.h>
#include <math.h>
#include <cstdint>

#define BN 8192
#define DD 128
#define NT (BN/128)                 // 64 tiles per dim
#define NBLK (NT*(NT+1)/2)          // 2080 triangular tiles
#define FARV (-0.00995033085316808285f)

#define RS   272                    // padded smem row stride (bytes): conflict-free
#define RSU4 17                     // row stride in uint4
#define TILE128 (128*RS)            // 34816 B
#define TILE64  (64*RS)             // 17408 B

// Device state. g_h / g_wt are PLAIN row-major bf16 (256B rows); padding is
// applied only when staging into smem (dst uint4 index = e + (e>>4)).
__device__ __nv_bfloat16 g_h[BN*DD];
__device__ __nv_bfloat16 g_wt[3][DD*DD];   // row n = column n of W
__device__ float  g_sq[BN];
__device__ double g_loss;
__device__ double g_hsum;
__device__ unsigned g_ticket;

// ---------------- warp-MMA helpers (plain sm_80+ PTX) ----------------------
__device__ __forceinline__ void ldm_x4(uint32_t& r0, uint32_t& r1,
                                       uint32_t& r2, uint32_t& r3, uint32_t addr) {
    asm volatile("ldmatrix.sync.aligned.m8n8.x4.shared.b16 {%0,%1,%2,%3}, [%4];"
                 : "=r"(r0), "=r"(r1), "=r"(r2), "=r"(r3) : "r"(addr));
}
__device__ __forceinline__ void mma_bf16(float* d, const uint32_t* a, const uint32_t* b) {
    asm volatile("mma.sync.aligned.m16n8k16.row.col.f32.bf16.bf16.f32 "
                 "{%0,%1,%2,%3}, {%4,%5,%6,%7}, {%8,%9}, {%0,%1,%2,%3};"
                 : "+f"(d[0]), "+f"(d[1]), "+f"(d[2]), "+f"(d[3])
                 : "r"(a[0]), "r"(a[1]), "r"(a[2]), "r"(a[3]), "r"(b[0]), "r"(b[1]));
}
__device__ __forceinline__ uint32_t smem_to_u32(const void* p) {
    uint32_t a;
    asm("{ .reg .u64 t; cvta.to.shared.u64 t, %1; cvt.u32.u64 %0, t; }" : "=r"(a) : "l"(p));
    return a;
}

// ---------------------------------------------------------------------------
// Prep (3 CTAs): coalesced stage of W into smem, transpose+round -> g_wt.
// ---------------------------------------------------------------------------
__global__ void __launch_bounds__(256)
k_prep(const float* __restrict__ W1, const float* __restrict__ W2,
       const float* __restrict__ W3) {
    extern __shared__ float stage[];   // 64KB fp32
    int tid = threadIdx.x, b = blockIdx.x;
    const float* W = (b == 0) ? W1 : (b == 1) ? W2 : W3;
    const float4* ws = (const float4*)W;
    float4* st4 = (float4*)stage;
    for (int e = tid; e < 4096; e += 256) st4[e] = ws[e];
    __syncthreads();
    uint4* dst = (uint4*)g_wt[b];
    for (int cid = tid; cid < 2048; cid += 256) {
        int c = cid >> 7, n = cid & 127;
        uint32_t pk[4];
        #pragma unroll
        for (int p = 0; p < 4; p++) {
            float lo = stage[(c*8 + 2*p    ) * DD + n];
            float hi = stage[(c*8 + 2*p + 1) * DD + n];
            __nv_bfloat162 h2 = __float22bfloat162_rn(make_float2(lo, hi));
            pk[p] = *(const uint32_t*)&h2;
        }
        dst[n*16 + c] = make_uint4(pk[0], pk[1], pk[2], pk[3]);
    }
    if (b == 0 && tid == 0) { g_loss = 0.0; g_hsum = 0.0; g_ticket = 0u; }
}

// ---------------------------------------------------------------------------
// Tensor-core MLP: 128 CTAs x 64 rows; 8 warps as 2x4 (wr rows, wc cols).
// Padded-row affine layout, fully unrolled k loop. 3 CTAs/SM.
// smem: header 1KB | A(64r) | B(64r) | W(128r)
// ---------------------------------------------------------------------------
#define MLP_A 1024
#define MLP_B (1024 + TILE64)
#define MLP_W (1024 + 2*TILE64)
#define MLP_SMEM (1024 + 2*TILE64 + TILE128)

__device__ __forceinline__ void mlp_mma(const char* smc, int aOff, float acc[2][4][4],
                                        int lane, int wr, int wc) {
    uint32_t aB = smem_to_u32(smc + aOff);
    uint32_t wB = smem_to_u32(smc + MLP_W);
    #pragma unroll
    for (int mt = 0; mt < 2; mt++)
        #pragma unroll
        for (int nt = 0; nt < 4; nt++)
            #pragma unroll
            for (int k = 0; k < 4; k++) acc[mt][nt][k] = 0.0f;

    int bg = lane >> 3;
    uint32_t aA0 = aB + (uint32_t)(wr*32 + (lane & 15))*RS + (uint32_t)(lane >> 4)*16;
    uint32_t bA0 = wB + (uint32_t)(wc*32 + ((bg >> 1) << 3) + (lane & 7))*RS
                 + (uint32_t)(bg & 1)*16;

    #pragma unroll
    for (int ks = 0; ks < 8; ks++) {
        uint32_t a[2][4];
        ldm_x4(a[0][0], a[0][1], a[0][2], a[0][3], aA0 + ks*32);
        ldm_x4(a[1][0], a[1][1], a[1][2], a[1][3], aA0 + 16*RS + ks*32);
        uint32_t bfr[4][2];
        {
            uint32_t r0, r1, r2, r3;
            ldm_x4(r0, r1, r2, r3, bA0 + ks*32);
            bfr[0][0] = r0; bfr[0][1] = r1; bfr[1][0] = r2; bfr[1][1] = r3;
            ldm_x4(r0, r1, r2, r3, bA0 + 16*RS + ks*32);
            bfr[2][0] = r0; bfr[2][1] = r1; bfr[3][0] = r2; bfr[3][1] = r3;
        }
        #pragma unroll
        for (int mt = 0; mt < 2; mt++)
            #pragma unroll
            for (int nt = 0; nt < 4; nt++)
                mma_bf16(acc[mt][nt], a[mt], bfr[nt]);
    }
}

template<bool RELU, bool LAST>
__device__ __forceinline__ void mlp_store(char* smc, int outOff, float acc[2][4][4],
                                          int lane, int wr, int wc) {
    const float* biasf = (const float*)smc;
    float* sq_sm = (float*)(smc + 512);
    int r8 = lane >> 2, c2 = (lane & 3) << 1;
    #pragma unroll
    for (int mt = 0; mt < 2; mt++) {
        float srow[2] = {0.0f, 0.0f};
        #pragma unroll
        for (int nt = 0; nt < 4; nt++) {
            int col = wc*32 + nt*8 + c2;
            float b0 = biasf[col], b1 = biasf[col + 1];
            #pragma unroll
            for (int h8 = 0; h8 < 2; h8++) {
                float f0 = acc[mt][nt][h8*2]     + b0;
                float f1 = acc[mt][nt][h8*2 + 1] + b1;
                if (RELU) { f0 = fmaxf(f0, 0.0f); f1 = fmaxf(f1, 0.0f); }
                __nv_bfloat162 p = __float22bfloat162_rn(make_float2(f0, f1));
                uint32_t pk = *(const uint32_t*)&p;
                int r = wr*32 + mt*16 + h8*8 + r8;
                int chunk = wc*4 + nt;
                uint32_t off = (uint32_t)outOff + (uint32_t)r*RS
                             + (uint32_t)chunk*16 + (uint32_t)c2*2;
                *(uint32_t*)(smc + off) = pk;
                if (LAST) {
                    float2 fb = __bfloat1622float2(p);
                    srow[h8] += fb.x*fb.x + fb.y*fb.y;
                }
            }
        }
        if (LAST) {
            #pragma unroll
            for (int h8 = 0; h8 < 2; h8++) {
                float s = srow[h8];
                s += __shfl_xor_sync(0xffffffffu, s, 1);
                s += __shfl_xor_sync(0xffffffffu, s, 2);
                if ((lane & 3) == 0)
                    atomicAdd(&sq_sm[wr*32 + mt*16 + h8*8 + r8], s);
            }
        }
    }
}

__global__ void __launch_bounds__(256, 3)
k_mlp(const float* __restrict__ X, const float* __restrict__ b1,
      const float* __restrict__ b2, const float* __restrict__ b3) {
    extern __shared__ char smc[];
    float* biasf = (float*)smc;           // 512B
    float* sq_sm = (float*)(smc + 512);   // 256B
    float* red   = (float*)(smc + 768);   // 32B

    int tid = threadIdx.x, wid = tid >> 5, lane = tid & 31;
    int wr = wid & 1, wc = wid >> 1;
    int r0 = blockIdx.x * 64;

    uint4* Au4 = (uint4*)(smc + MLP_A);
    uint4* Wu4 = (uint4*)(smc + MLP_W);

    // load X rows fp32 (coalesced), round bf16, store padded
    const float4* src = (const float4*)(X + r0*DD);
    for (int e = tid; e < 1024; e += 256) {
        int row = e >> 4, c = e & 15;
        float4 v0 = src[row*32 + c*2];
        float4 v1 = src[row*32 + c*2 + 1];
        __nv_bfloat162 p0 = __float22bfloat162_rn(make_float2(v0.x, v0.y));
        __nv_bfloat162 p1 = __float22bfloat162_rn(make_float2(v0.z, v0.w));
        __nv_bfloat162 p2 = __float22bfloat162_rn(make_float2(v1.x, v1.y));
        __nv_bfloat162 p3 = __float22bfloat162_rn(make_float2(v1.z, v1.w));
        Au4[row*RSU4 + c] = make_uint4(*(const uint32_t*)&p0, *(const uint32_t*)&p1,
                                       *(const uint32_t*)&p2, *(const uint32_t*)&p3);
    }
    for (int e = tid; e < 2048; e += 256) Wu4[e + (e >> 4)] = ((const uint4*)g_wt[0])[e];
    if (tid < DD) biasf[tid] = b1[tid];
    if (tid < 64) sq_sm[tid] = 0.0f;
    __syncthreads();

    float acc[2][4][4];

    // layer 1: A -> B
    mlp_mma(smc, MLP_A, acc, lane, wr, wc);
    __syncthreads();
    mlp_store<true, false>(smc, MLP_B, acc, lane, wr, wc);
    for (int e = tid; e < 2048; e += 256) Wu4[e + (e >> 4)] = ((const uint4*)g_wt[1])[e];
    __syncthreads();
    if (tid < DD) biasf[tid] = b2[tid];
    __syncthreads();

    // layer 2: B -> A
    mlp_mma(smc, MLP_B, acc, lane, wr, wc);
    __syncthreads();
    mlp_store<true, false>(smc, MLP_A, acc, lane, wr, wc);
    for (int e = tid; e < 2048; e += 256) Wu4[e + (e >> 4)] = ((const uint4*)g_wt[2])[e];
    __syncthreads();
    if (tid < DD) biasf[tid] = b3[tid];
    __syncthreads();

    // layer 3: A -> B (no relu), sq from rounded values
    mlp_mma(smc, MLP_A, acc, lane, wr, wc);
    __syncthreads();
    mlp_store<false, true>(smc, MLP_B, acc, lane, wr, wc);
    __syncthreads();

    // write h block: padded smem -> plain g_h rows
    for (int e = tid; e < 1024; e += 256) {
        int row = e >> 4;
        ((uint4*)g_h)[(r0 + row)*16 + (e & 15)] = ((uint4*)(smc + MLP_B))[e + row];
    }
    if (tid < 64) {
        float sv = sq_sm[tid];
        g_sq[r0 + tid] = sv;
        sv += __shfl_xor_sync(0xffffffffu, sv, 16);
        sv += __shfl_xor_sync(0xffffffffu, sv, 8);
        sv += __shfl_xor_sync(0xffffffffu, sv, 4);
        sv += __shfl_xor_sync(0xffffffffu, sv, 2);
        sv += __shfl_xor_sync(0xffffffffu, sv, 1);
        if (lane == 0) red[wid] = sv;
    }
    __syncthreads();
    if (tid == 0) atomicAdd(&g_hsum, (double)(red[0] + red[1]));
}

// ---------------------------------------------------------------------------
// Pairwise: one 128x128 tile per CTA, 2080 CTAs. Padded-row layout, full
// unroll, n-split into two halves (acc 32 regs) => 3 CTAs/SM.
// smem: header 4KB | Hi(128r) | Hj(128r) = 73728 B
// ---------------------------------------------------------------------------
#define HI_OFF 4096
#define HJ_OFF (4096 + TILE128)
#define PAIR_SMEM (4096 + 2*TILE128)

__global__ void __launch_bounds__(256, 3)
k_pair(const int* __restrict__ y, float* __restrict__ out) {
    extern __shared__ char smc[];
    float* redf = (float*)(smc + 16);
    float* sqi  = (float*)(smc + 64);
    float* sqj  = (float*)(smc + 576);
    int*   yi   = (int*)(smc + 1088);
    int*   yj   = (int*)(smc + 1600);

    int tid = threadIdx.x, wid = tid >> 5, lane = tid & 31;
    int wr = wid & 3, wc = wid >> 2;

    // triangular tile mapping: block t -> (bi, bj) with bi <= bj
    int t = blockIdx.x;
    float nf = (float)NT + 0.5f;
    int bi = (int)(nf - sqrtf(nf*nf - 2.0f*(float)t));
    if (bi < 0) bi = 0;
    if (bi >= NT) bi = NT - 1;
    while (bi*NT - (bi*(bi-1))/2 > t) bi--;
    while ((bi+1)*NT - ((bi+1)*bi)/2 <= t) bi++;
    int bj = bi + (t - (bi*NT - (bi*(bi-1))/2));

    // tile loads: plain g_h rows -> padded smem
    const uint4* gh = (const uint4*)g_h;
    uint4* Hi = (uint4*)(smc + HI_OFF);
    uint4* Hj = (uint4*)(smc + HJ_OFF);
    for (int e = tid; e < 2048; e += 256) {
        int pad = e >> 4;
        Hi[e + pad] = gh[bi*2048 + e];
        Hj[e + pad] = gh[bj*2048 + e];
    }
    if (tid < 128) {
        sqi[tid] = g_sq[bi*128 + tid];
        sqj[tid] = g_sq[bj*128 + tid];
        yi[tid]  = y[bi*128 + tid];
        yj[tid]  = y[bj*128 + tid];
    }
    __syncthreads();

    uint32_t hiB = smem_to_u32(smc + HI_OFF);
    uint32_t hjB = smem_to_u32(smc + HJ_OFF);

    int bg = lane >> 3;
    uint32_t aA0 = hiB + (uint32_t)(wr*32 + (lane & 15))*RS + (uint32_t)(lane >> 4)*16;
    uint32_t bBase = hjB + (uint32_t)(((bg >> 1) << 3) + (lane & 7))*RS
                   + (uint32_t)(bg & 1)*16;

    int r8 = lane >> 2, c2 = (lane & 3) << 1;
    float si[2][2]; int li[2][2];
    #pragma unroll
    for (int mt = 0; mt < 2; mt++)
        #pragma unroll
        for (int h = 0; h < 2; h++) {
            int row = wr*32 + mt*16 + h*8 + r8;
            si[mt][h] = sqi[row];
            li[mt][h] = yi[row];
        }

    float lsum = 0.0f;

    #pragma unroll 1
    for (int p = 0; p < 2; p++) {
        uint32_t bA0 = bBase + (uint32_t)(wc*64 + p*32)*RS;

        float acc[2][4][4];
        #pragma unroll
        for (int mt = 0; mt < 2; mt++)
            #pragma unroll
            for (int nt = 0; nt < 4; nt++)
                #pragma unroll
                for (int k = 0; k < 4; k++) acc[mt][nt][k] = 0.0f;

        #pragma unroll
        for (int ks = 0; ks < 8; ks++) {
            uint32_t a[2][4];
            ldm_x4(a[0][0], a[0][1], a[0][2], a[0][3], aA0 + ks*32);
            ldm_x4(a[1][0], a[1][1], a[1][2], a[1][3], aA0 + 16*RS + ks*32);
            uint32_t bfr[4][2];
            {
                uint32_t r0, r1, r2, r3;
                ldm_x4(r0, r1, r2, r3, bA0 + ks*32);
                bfr[0][0] = r0; bfr[0][1] = r1; bfr[1][0] = r2; bfr[1][1] = r3;
                ldm_x4(r0, r1, r2, r3, bA0 + 16*RS + ks*32);
                bfr[2][0] = r0; bfr[2][1] = r1; bfr[3][0] = r2; bfr[3][1] = r3;
            }
            #pragma unroll
            for (int mt = 0; mt < 2; mt++)
                #pragma unroll
                for (int nt = 0; nt < 4; nt++)
                    mma_bf16(acc[mt][nt], a[mt], bfr[nt]);
        }

        // epilogue for this half
        float sj[4][2]; int lj[4][2];
        #pragma unroll
        for (int nt = 0; nt < 4; nt++)
            #pragma unroll
            for (int q = 0; q < 2; q++) {
                int col = wc*64 + p*32 + nt*8 + c2 + q;
                sj[nt][q] = sqj[col];
                lj[nt][q] = yj[col];
            }

        int rare = 0;
        #pragma unroll
        for (int mt = 0; mt < 2; mt++)
            #pragma unroll
            for (int nt = 0; nt < 4; nt++)
                #pragma unroll
                for (int h = 0; h < 2; h++)
                    #pragma unroll
                    for (int q = 0; q < 2; q++) {
                        float d = acc[mt][nt][h*2 + q];
                        float dist = fmaf(-2.0f, d, si[mt][h] + sj[nt][q]);
                        bool  eq = (li[mt][h] == lj[nt][q]);
                        lsum += eq ? dist : FARV;
                        rare |= (!eq && dist < 18.0f);
                    }
        if (__any_sync(0xffffffffu, rare)) {
            #pragma unroll
            for (int mt = 0; mt < 2; mt++)
                #pragma unroll
                for (int nt = 0; nt < 4; nt++)
                    #pragma unroll
                    for (int h = 0; h < 2; h++)
                        #pragma unroll
                        for (int q = 0; q < 2; q++) {
                            float d = acc[mt][nt][h*2 + q];
                            float dist = fmaxf(fmaf(-2.0f, d, si[mt][h] + sj[nt][q]), 0.0f);
                            bool  eq = (li[mt][h] == lj[nt][q]);
                            if (!eq && dist < 18.0f)
                                lsum += (-logf(1.01f - expf(-dist))) - FARV;
                        }
        }
    }

    lsum += __shfl_xor_sync(0xffffffffu, lsum, 1);
    lsum += __shfl_xor_sync(0xffffffffu, lsum, 2);
    lsum += __shfl_xor_sync(0xffffffffu, lsum, 4);
    lsum += __shfl_xor_sync(0xffffffffu, lsum, 8);
    lsum += __shfl_xor_sync(0xffffffffu, lsum, 16);
    if (lane == 0) redf[wid] = lsum;
    __syncthreads();
    if (tid == 0) {
        double tot = 0.0;
        for (int w = 0; w < 8; w++) tot += (double)redf[w];
        if (bi != bj) tot *= 2.0;
        atomicAdd(&g_loss, tot);
        __threadfence();
        unsigned tk = atomicAdd(&g_ticket, 1u);
        if (tk == NBLK - 1) {
            __threadfence();
            double lt = atomicAdd(&g_loss, 0.0);
            double hs = atomicAdd(&g_hsum, 0.0);
            double loss = lt / ((double)BN * (double)BN);
            loss += 0.01 * (hs / ((double)BN * (double)DD));
            out[0] = (float)loss;
        }
    }
}

// ---------------------------------------------------------------------------

extern "C" void kernel_launch(void* const* d_in, const int* in_sizes, int n_in,
                              void* d_out, int out_size) {
    (void)in_sizes; (void)n_in; (void)out_size;
    const float* X  = (const float*)d_in[0];
    const float* W1 = (const float*)d_in[1];
    const float* b1 = (const float*)d_in[2];
    const float* W2 = (const float*)d_in[3];
    const float* b2 = (const float*)d_in[4];
    const float* W3 = (const float*)d_in[5];
    const float* b3 = (const float*)d_in[6];
    const int*   y  = (const int*)d_in[7];

    cudaFuncSetAttribute(k_prep, cudaFuncAttributeMaxDynamicSharedMemorySize, 65536);
    cudaFuncSetAttribute(k_mlp,  cudaFuncAttributeMaxDynamicSharedMemorySize, MLP_SMEM);
    cudaFuncSetAttribute(k_pair, cudaFuncAttributeMaxDynamicSharedMemorySize, PAIR_SMEM);

    k_prep<<<3, 256, 65536>>>(W1, W2, W3);
    k_mlp<<<BN/64, 256, MLP_SMEM>>>(X, b1, b2, b3);
    k_pair<<<NBLK, 256, PAIR_SMEM>>>(y, (float*)d_out);
}